// round 12
// baseline (speedup 1.0000x reference)
#include <cuda_runtime.h>
#include <cstdint>

typedef unsigned long long u64;

#define T_STEPS 256
#define BATCH   8192
#define GSTEPS  8            // steps per pipeline stage
#define NGROUPS (T_STEPS / GSTEPS)   // 32

__device__ __forceinline__ void ffma2(u64& acc, u64 a, u64 b) {
    asm("fma.rn.f32x2 %0, %1, %2, %0;" : "+l"(acc) : "l"(a), "l"(b));
}
__device__ __forceinline__ u64 fadd2(u64 a, u64 b) {
    u64 d; asm("add.rn.f32x2 %0, %1, %2;" : "=l"(d) : "l"(a), "l"(b)); return d;
}
__device__ __forceinline__ u64 pack2(float lo, float hi) {
    u64 v; asm("mov.b64 %0, {%1, %2};" : "=l"(v) : "f"(lo), "f"(hi)); return v;
}
__device__ __forceinline__ float2 unpack2(u64 v) {
    float2 r; asm("mov.b64 {%0, %1}, %2;" : "=f"(r.x), "=f"(r.y) : "l"(v)); return r;
}
__device__ __forceinline__ unsigned smem_u32(const void* p) {
    unsigned a;
    asm("{ .reg .u64 t; cvta.to.shared.u64 t, %1; cvt.u32.u64 %0, t; }" : "=r"(a) : "l"(p));
    return a;
}
__device__ __forceinline__ void mbar_init(unsigned addr, unsigned count) {
    asm volatile("mbarrier.init.shared.b64 [%0], %1;" :: "r"(addr), "r"(count) : "memory");
}
__device__ __forceinline__ void mbar_arrive(unsigned addr) {
    asm volatile("mbarrier.arrive.shared.b64 _, [%0];" :: "r"(addr) : "memory");
}
__device__ __forceinline__ void mbar_expect_tx(unsigned addr, unsigned bytes) {
    asm volatile("mbarrier.arrive.expect_tx.shared.b64 _, [%0], %1;"
                 :: "r"(addr), "r"(bytes) : "memory");
}
__device__ __forceinline__ void mbar_wait(unsigned addr, unsigned parity) {
    asm volatile(
        "{\n\t.reg .pred P;\n\t"
        "W%=:\n\t"
        "mbarrier.try_wait.parity.acquire.cta.shared::cta.b64 P, [%0], %1, 0x989680;\n\t"
        "@P bra D%=;\n\t"
        "bra W%=;\n\t"
        "D%=:\n\t}"
        :: "r"(addr), "r"(parity) : "memory");
}
__device__ __forceinline__ void bulk_cp(unsigned dst, const void* src, unsigned bytes,
                                        unsigned mbar) {
    asm volatile(
        "cp.async.bulk.shared::cta.global.mbarrier::complete_tx::bytes [%0], [%1], %2, [%3];"
        :: "r"(dst), "l"(src), "r"(bytes), "r"(mbar) : "memory");
}

// One warp = one batch element; 8 warps/CTA. Lane j<28 owns L1 neuron j,
// lane j<14 owns L2 neuron j. Spikes via ballot; W2/W3 via smem LUTs.
// x delivered per-CTA via cp.async.bulk double-buffer (8 steps/stage),
// one producer thread, mbarrier full/empty handshake. No per-lane LDGSTS,
// no __syncwarp in the hot loop.
// NOTE: GEMM accumulation order is part of the correctness contract.
__global__ __launch_bounds__(256, 2)
void snn_all(const float* __restrict__ x,
             const float* __restrict__ W1, const float* __restrict__ b1,
             const float* __restrict__ W2, const float* __restrict__ b2,
             const float* __restrict__ W3, const float* __restrict__ b3,
             float* __restrict__ out)
{
    __shared__ __align__(128) u64 xbuf[2][GSTEPS][8][32];   // 32 KB: [stage][step][elem][256B]
    __shared__ float LUT2[4][128][16];                      // 32 KB
    __shared__ float L3s[2][128];                           // 1 KB
    __shared__ __align__(8) u64 mbar_store[4];              // full0, full1, empty0, empty1

    const int tid = threadIdx.x;
    const unsigned mb = smem_u32(mbar_store);
    #define FULLB(s)  (mb + (unsigned)(s) * 8u)
    #define EMPTYB(s) (mb + 16u + (unsigned)(s) * 8u)

    // ---- build LUTs ----
    for (int e = tid; e < 512; e += 256) {
        const int g = e >> 7, m = e & 127;
        #pragma unroll
        for (int j = 0; j < 16; j++) {
            float s = 0.0f;
            if (j < 14) {
                #pragma unroll
                for (int k = 0; k < 7; k++)
                    if (m & (1 << k)) s += W2[j * 28 + 7 * g + k];
            }
            LUT2[g][m][j] = s;
        }
    }
    {
        const int g = tid >> 7, m = tid & 127;
        float s = 0.0f;
        #pragma unroll
        for (int k = 0; k < 7; k++)
            if (m & (1 << k)) s += W3[7 * g + k];
        L3s[g][m] = s;
    }

    const int lane = tid & 31;
    const int w    = tid >> 5;
    const int b    = blockIdx.x * 8 + w;
    const int j1   = (lane < 28) ? lane : 27;
    const int j2   = (lane < 14) ? lane : 13;

    // ---- W1 row in registers (packed f32x2) ----
    u64 w1r[32];
    {
        const float4* wp = (const float4*)(W1 + j1 * 64);
        #pragma unroll
        for (int k = 0; k < 16; k++) {
            float4 v = wp[k];
            w1r[2*k]   = pack2(v.x, v.y);
            w1r[2*k+1] = pack2(v.z, v.w);
        }
    }
    const float b1j = b1[j1];
    const float b2j = b2[j2];
    const float b3v = b3[0];

    if (tid == 0) {
        mbar_init(FULLB(0), 1);  mbar_init(FULLB(1), 1);
        mbar_init(EMPTYB(0), 8); mbar_init(EMPTYB(1), 8);
    }
    __syncthreads();   // LUTs + barriers ready

    // ---- producer state ----
    const float* xsrc = x + (size_t)blockIdx.x * 8 * 64;   // 2KB slab per t
    const size_t tstride = (size_t)BATCH * 64;             // floats between t
    const unsigned xb = smem_u32(xbuf);

    #define PRODUCE(g) do {                                                     \
        const int s_ = (g) & 1;                                                 \
        mbar_expect_tx(FULLB(s_), GSTEPS * 2048u);                              \
        _Pragma("unroll")                                                       \
        for (int st = 0; st < GSTEPS; st++)                                     \
            bulk_cp(xb + (unsigned)s_ * 16384u + (unsigned)st * 2048u,          \
                    xsrc + (size_t)((g) * GSTEPS + st) * tstride,               \
                    2048u, FULLB(s_));                                          \
    } while (0)

    if (tid == 0) { PRODUCE(0); PRODUCE(1); }

    float m1 = 0.0f, m2 = 0.0f, m3 = 0.0f;

    #define LIF_STEP(t, cur1) do {                                              \
        float r1 = (m1 > 1.0f) ? 1.0f : 0.0f;                                   \
        m1 = fmaf(0.9f, m1, (cur1)) - r1;                                       \
        unsigned s1 = __ballot_sync(0xffffffffu, m1 > 1.0f) & 0x0FFFFFFFu;      \
        float cur2 = b2j + (LUT2[0][s1 & 127u][j2]                              \
                          + LUT2[1][(s1 >> 7) & 127u][j2])                      \
                         + (LUT2[2][(s1 >> 14) & 127u][j2]                      \
                          + LUT2[3][s1 >> 21][j2]);                             \
        float r2 = (m2 > 1.0f) ? 1.0f : 0.0f;                                   \
        m2 = fmaf(0.9f, m2, cur2) - r2;                                         \
        unsigned s2 = __ballot_sync(0xffffffffu, m2 > 1.0f) & 0x3FFFu;          \
        float cur3 = b3v + (L3s[0][s2 & 127u] + L3s[1][s2 >> 7]);               \
        float r3 = (m3 > 1.0f) ? 1.0f : 0.0f;                                   \
        m3 = fmaf(0.9f, m3, cur3) - r3;                                         \
        if (lane == 0) out[(size_t)(t) * BATCH + b] = m3;                       \
    } while (0)

    // layer-1 dot product — EXACT 4-accumulator order (contract)
    #define GEMM(sg, st, cur1) do {                                             \
        const ulonglong2* xv = (const ulonglong2*)&xbuf[(sg)][(st)][w][0];      \
        u64 a0 = pack2(b1j, 0.0f), a1 = 0ull, a2 = 0ull, a3 = 0ull;             \
        _Pragma("unroll")                                                       \
        for (int k = 0; k < 8; k++) {                                           \
            ulonglong2 p = xv[2*k];                                             \
            ulonglong2 q = xv[2*k+1];                                           \
            ffma2(a0, p.x, w1r[4*k]);                                           \
            ffma2(a1, p.y, w1r[4*k+1]);                                         \
            ffma2(a2, q.x, w1r[4*k+2]);                                         \
            ffma2(a3, q.y, w1r[4*k+3]);                                         \
        }                                                                       \
        float2 c = unpack2(fadd2(fadd2(a0, a1), fadd2(a2, a3)));                \
        (cur1) = c.x + c.y;                                                     \
    } while (0)

    #pragma unroll 1
    for (int g = 0; g < NGROUPS; g++) {
        const int s  = g & 1;
        const unsigned ph = (unsigned)((g >> 1) & 1);
        mbar_wait(FULLB(s), ph);                     // stage data ready

        const int t0 = g * GSTEPS;

        // half 1: 4 GEMMs hoisted, then 4 LIF chains
        float c0, c1, c2, c3;
        GEMM(s, 0, c0); GEMM(s, 1, c1); GEMM(s, 2, c2); GEMM(s, 3, c3);
        LIF_STEP(t0 + 0, c0); LIF_STEP(t0 + 1, c1);
        LIF_STEP(t0 + 2, c2); LIF_STEP(t0 + 3, c3);

        // half 2
        GEMM(s, 4, c0); GEMM(s, 5, c1); GEMM(s, 6, c2); GEMM(s, 7, c3);
        LIF_STEP(t0 + 4, c0); LIF_STEP(t0 + 5, c1);
        LIF_STEP(t0 + 6, c2); LIF_STEP(t0 + 7, c3);

        if (lane == 0) mbar_arrive(EMPTYB(s));       // warp done with stage s
        if (tid == 0 && g + 2 < NGROUPS) {
            mbar_wait(EMPTYB(s), ph);                // all 8 warps done
            PRODUCE(g + 2);
        }
    }
    #undef GEMM
    #undef LIF_STEP
    #undef PRODUCE
    #undef FULLB
    #undef EMPTYB
}

extern "C" void kernel_launch(void* const* d_in, const int* in_sizes, int n_in,
                              void* d_out, int out_size) {
    const float* x  = (const float*)d_in[0];
    const float* W1 = (const float*)d_in[1];
    const float* b1 = (const float*)d_in[2];
    const float* W2 = (const float*)d_in[3];
    const float* b2 = (const float*)d_in[4];
    const float* W3 = (const float*)d_in[5];
    const float* b3 = (const float*)d_in[6];
    snn_all<<<BATCH / 8, 256>>>(x, W1, b1, W2, b2, W3, b3, (float*)d_out);
}

// round 13
// speedup vs baseline: 1.8024x; 1.8024x over previous
#include <cuda_runtime.h>
#include <cstdint>

typedef unsigned long long u64;

#define T_STEPS 256
#define BATCH   8192
#define DEPTH   16           // ring slots (steps); commit granularity = 4 steps

__device__ __forceinline__ void ffma2(u64& acc, u64 a, u64 b) {
    asm("fma.rn.f32x2 %0, %1, %2, %0;" : "+l"(acc) : "l"(a), "l"(b));
}
__device__ __forceinline__ u64 fadd2(u64 a, u64 b) {
    u64 d; asm("add.rn.f32x2 %0, %1, %2;" : "=l"(d) : "l"(a), "l"(b)); return d;
}
__device__ __forceinline__ u64 pack2(float lo, float hi) {
    u64 v; asm("mov.b64 %0, {%1, %2};" : "=l"(v) : "f"(lo), "f"(hi)); return v;
}
__device__ __forceinline__ float2 unpack2(u64 v) {
    float2 r; asm("mov.b64 {%0, %1}, %2;" : "=f"(r.x), "=f"(r.y) : "l"(v)); return r;
}
__device__ __forceinline__ unsigned smem_u32(const void* p) {
    unsigned a;
    asm("{ .reg .u64 t; cvta.to.shared.u64 t, %1; cvt.u32.u64 %0, t; }" : "=r"(a) : "l"(p));
    return a;
}
__device__ __forceinline__ void cp_async16(unsigned dst, const void* src) {
    asm volatile("cp.async.ca.shared.global [%0], [%1], 16;" :: "r"(dst), "l"(src));
}
__device__ __forceinline__ void cp_commit() {
    asm volatile("cp.async.commit_group;" ::: "memory");
}
__device__ __forceinline__ void cp_wait3() {
    asm volatile("cp.async.wait_group 3;" ::: "memory");
}

// One warp = one batch element. Lane j<28 owns L1 neuron j; lane j<14 owns L2
// neuron j. Spikes via ballot; W2/W3 sums via smem LUTs (7-bit mask groups).
// x streamed via per-warp cp.async ring; 4 steps per commit/wait/sync block
// delivered as 2x512B cp.async (16B/lane, two ring slots per instruction).
// NOTE: GEMM accumulation order is part of the correctness contract (spike
// decisions flip under reassociation) — keep the 4-chain order exactly.
__global__ __launch_bounds__(256, 2)
void snn_all(const float* __restrict__ x,
             const float* __restrict__ W1, const float* __restrict__ b1,
             const float* __restrict__ W2, const float* __restrict__ b2,
             const float* __restrict__ W3, const float* __restrict__ b3,
             float* __restrict__ out)
{
    __shared__ __align__(16) u64 xring[8][DEPTH][32];   // 32 KB
    __shared__ float LUT2[4][128][16];                  // 32 KB (j padded 14->16)
    __shared__ float L3s[2][128];                       // 1 KB

    const int tid = threadIdx.x;

    // ---- build LUTs: LUT2[g][m][j] = sum_{k: m bit k} W2[j, 7g+k] ----
    for (int e = tid; e < 512; e += 256) {
        const int g = e >> 7, m = e & 127;
        #pragma unroll
        for (int j = 0; j < 16; j++) {
            float s = 0.0f;
            if (j < 14) {
                #pragma unroll
                for (int k = 0; k < 7; k++)
                    if (m & (1 << k)) s += W2[j * 28 + 7 * g + k];
            }
            LUT2[g][m][j] = s;
        }
    }
    {
        const int g = tid >> 7, m = tid & 127;
        float s = 0.0f;
        #pragma unroll
        for (int k = 0; k < 7; k++)
            if (m & (1 << k)) s += W3[7 * g + k];
        L3s[g][m] = s;
    }

    const int lane = tid & 31;
    const int w    = tid >> 5;
    const int b    = blockIdx.x * 8 + w;
    const int j1   = (lane < 28) ? lane : 27;
    const int j2   = (lane < 14) ? lane : 13;

    // ---- W1 row in registers (packed f32x2) ----
    u64 w1r[32];
    {
        const float4* wp = (const float4*)(W1 + j1 * 64);
        #pragma unroll
        for (int k = 0; k < 16; k++) {
            float4 v = wp[k];
            w1r[2*k]   = pack2(v.x, v.y);
            w1r[2*k+1] = pack2(v.z, v.w);
        }
    }
    const float b1j = b1[j1];
    const float b2j = b2[j2];
    const float b3v = b3[0];

    __syncthreads();   // LUTs ready

    // ---- cp.async ring: block of 4 steps = 1KB = 2 x 512B instructions.
    // Lane l covers slot (t + (l>>4) [+2]) at byte (l&15)*16.
    const int lhi = lane >> 4;          // 0 or 1: which slot of the pair
    const int llo = lane & 15;          // 16B chunk within a 256B slot
    const float* xg2 = x + (size_t)b * 64 + llo * 4;
    const size_t tstride = (size_t)BATCH * 64;
    const unsigned ringq = smem_u32(&xring[w][0][0]) + (unsigned)(llo * 16);

    #define PRODUCE(tt) do {                                                    \
        const int sb_ = (tt) & (DEPTH - 1);                                     \
        cp_async16(ringq + (unsigned)((sb_ + lhi) * 256),                       \
                   xg2 + (size_t)((tt) + lhi) * tstride);                       \
        cp_async16(ringq + (unsigned)((sb_ + 2 + lhi) * 256),                   \
                   xg2 + (size_t)((tt) + 2 + lhi) * tstride);                   \
        cp_commit();                                                            \
    } while (0)

    // prefill steps 0..11 (3 commit groups)
    PRODUCE(0); PRODUCE(4); PRODUCE(8);

    float m1 = 0.0f, m2 = 0.0f, m3 = 0.0f;

    #define LIF_STEP(t, cur1) do {                                              \
        float r1 = (m1 > 1.0f) ? 1.0f : 0.0f;                                   \
        m1 = fmaf(0.9f, m1, (cur1)) - r1;                                       \
        unsigned s1 = __ballot_sync(0xffffffffu, m1 > 1.0f) & 0x0FFFFFFFu;      \
        float cur2 = b2j + (LUT2[0][s1 & 127u][j2]                              \
                          + LUT2[1][(s1 >> 7) & 127u][j2])                      \
                         + (LUT2[2][(s1 >> 14) & 127u][j2]                      \
                          + LUT2[3][s1 >> 21][j2]);                             \
        float r2 = (m2 > 1.0f) ? 1.0f : 0.0f;                                   \
        m2 = fmaf(0.9f, m2, cur2) - r2;                                         \
        unsigned s2 = __ballot_sync(0xffffffffu, m2 > 1.0f) & 0x3FFFu;          \
        float cur3 = b3v + (L3s[0][s2 & 127u] + L3s[1][s2 >> 7]);               \
        float r3 = (m3 > 1.0f) ? 1.0f : 0.0f;                                   \
        m3 = fmaf(0.9f, m3, cur3) - r3;                                         \
        if (lane == 0) out[(size_t)(t) * BATCH + b] = m3;                       \
    } while (0)

    // layer-1 dot product from ring slot s — EXACT 4-accumulator order
    #define GEMM(s, cur1) do {                                                  \
        const ulonglong2* xv = (const ulonglong2*)&xring[w][(s)][0];            \
        u64 a0 = pack2(b1j, 0.0f), a1 = 0ull, a2 = 0ull, a3 = 0ull;             \
        _Pragma("unroll")                                                       \
        for (int k = 0; k < 8; k++) {                                           \
            ulonglong2 p = xv[2*k];                                             \
            ulonglong2 q = xv[2*k+1];                                           \
            ffma2(a0, p.x, w1r[4*k]);                                           \
            ffma2(a1, p.y, w1r[4*k+1]);                                         \
            ffma2(a2, q.x, w1r[4*k+2]);                                         \
            ffma2(a3, q.y, w1r[4*k+3]);                                         \
        }                                                                       \
        float2 c = unpack2(fadd2(fadd2(a0, a1), fadd2(a2, a3)));                \
        (cur1) = c.x + c.y;                                                     \
    } while (0)

    #pragma unroll 1
    for (int t = 0; t < T_STEPS; t += 4) {
        // issue group for steps t+12..t+15 (slots disjoint from t..t+3)
        const int tn = t + 12;
        if (tn < T_STEPS) {
            PRODUCE(tn);
        } else {
            cp_commit();       // keep outstanding-group count consistent
        }
        cp_wait3();            // group covering steps t..t+3 complete
        __syncwarp();

        // all four GEMMs first — independent of the recurrent chain
        float c0, c1, c2, c3;
        GEMM((t)     & (DEPTH - 1), c0);
        GEMM((t + 1) & (DEPTH - 1), c1);
        GEMM((t + 2) & (DEPTH - 1), c2);
        GEMM((t + 3) & (DEPTH - 1), c3);

        LIF_STEP(t,     c0);
        LIF_STEP(t + 1, c1);
        LIF_STEP(t + 2, c2);
        LIF_STEP(t + 3, c3);
    }
    #undef GEMM
    #undef LIF_STEP
    #undef PRODUCE
}

extern "C" void kernel_launch(void* const* d_in, const int* in_sizes, int n_in,
                              void* d_out, int out_size) {
    const float* x  = (const float*)d_in[0];
    const float* W1 = (const float*)d_in[1];
    const float* b1 = (const float*)d_in[2];
    const float* W2 = (const float*)d_in[3];
    const float* b2 = (const float*)d_in[4];
    const float* W3 = (const float*)d_in[5];
    const float* b3 = (const float*)d_in[6];
    snn_all<<<BATCH / 8, 256>>>(x, W1, b1, W2, b2, W3, b3, (float*)d_out);
}